// round 16
// baseline (speedup 1.0000x reference)
#include <cuda_runtime.h>
#include <cuda_fp16.h>
#include <math.h>
#include <stdint.h>

#define S_DIM 16
#define B_DIM 512
#define H_DIM 2048
#define EPS 1e-8f

// ---------------------------------------------------------------------------
// Device scratch (fp16 hi/lo of weightedRep)
// ---------------------------------------------------------------------------
__device__ __align__(16) __half g_Ahi[B_DIM * H_DIM];
__device__ __align__(16) __half g_Alo[B_DIM * H_DIM];

// ---------------------------------------------------------------------------
// PTX helpers (sm_80/90 baseline only — harness PTX target is sm_103, no 'a')
// ---------------------------------------------------------------------------
__device__ __forceinline__ uint32_t smem_u32(const void* p) {
    uint32_t r;
    asm("{ .reg .u64 t; cvta.to.shared.u64 t, %1; cvt.u32.u64 %0, t; }"
        : "=r"(r) : "l"(p));
    return r;
}
__device__ __forceinline__ void cpa16(uint32_t dst, const void* src) {
    asm volatile("cp.async.cg.shared.global [%0], [%1], 16;" :: "r"(dst), "l"(src));
}
#define CP_COMMIT() asm volatile("cp.async.commit_group;" ::: "memory")
#define CP_WAIT2()  asm volatile("cp.async.wait_group 2;" ::: "memory")
#define CP_WAIT0()  asm volatile("cp.async.wait_group 0;" ::: "memory")

__device__ __forceinline__ void ldsm4(uint32_t* r, uint32_t addr) {
    asm volatile("ldmatrix.sync.aligned.m8n8.x4.shared.b16 {%0,%1,%2,%3}, [%4];"
                 : "=r"(r[0]), "=r"(r[1]), "=r"(r[2]), "=r"(r[3]) : "r"(addr));
}
// fp16 MMA, fp32 accum
__device__ __forceinline__ void mma16816(float* d, const uint32_t* a,
                                         uint32_t b0, uint32_t b1) {
    asm volatile(
        "mma.sync.aligned.m16n8k16.row.col.f32.f16.f16.f32 "
        "{%0,%1,%2,%3}, {%4,%5,%6,%7}, {%8,%9}, {%0,%1,%2,%3};"
        : "+f"(d[0]), "+f"(d[1]), "+f"(d[2]), "+f"(d[3])
        : "r"(a[0]), "r"(a[1]), "r"(a[2]), "r"(a[3]), "r"(b0), "r"(b1));
}
__device__ __forceinline__ float dot4(float4 a, float4 b) {
    return a.x * b.x + a.y * b.y + a.z * b.z + a.w * b.w;
}
// fp32 pair -> fp16 hi pair + fp16 lo pair (packed u32); hi+lo ~= exact
__device__ __forceinline__ void split2h(float x, float y, uint32_t& h, uint32_t& l) {
    __half2 hh = __floats2half2_rn(x, y);
    float hx = __half2float(__low2half(hh));
    float hy = __half2float(__high2half(hh));
    __half2 ll = __floats2half2_rn(x - hx, y - hy);
    h = *reinterpret_cast<uint32_t*>(&hh);
    l = *reinterpret_cast<uint32_t*>(&ll);
}
__device__ __forceinline__ uint32_t cvt2h(float x, float y) {
    __half2 hh = __floats2half2_rn(x, y);
    return *reinterpret_cast<uint32_t*>(&hh);
}

// ---------------------------------------------------------------------------
// Kernel 1 (fused): norms + sims + weightedRep -> fp16 hi/lo  (R12 version)
// One CTA per b, 512 threads, warp w owns sample s = w.
// enhanced + OG staged via cp.async (all copies in flight before the wait).
// ---------------------------------------------------------------------------
#define SE_OFF 0
#define OG_OFF (S_DIM * (H_DIM / 4) * 16)            // 131072
#define FUSED_SMEM (OG_OFF + (H_DIM / 4) * 16)       // 139264

__global__ void __launch_bounds__(512, 1)
fused_prep(const float* __restrict__ og, const float* __restrict__ enh) {
    extern __shared__ __align__(16) char smc[];
    float4* se  = reinterpret_cast<float4*>(smc + SE_OFF);   // [S_DIM][H/4]
    float4* ogs = reinterpret_cast<float4*>(smc + OG_OFF);   // [H/4]
    __shared__ float sh_sims[S_DIM];

    const uint32_t sbase = smem_u32(smc);
    const int b = blockIdx.x;
    const int tid = threadIdx.x;
    const int wid = tid >> 5, lid = tid & 31;
    const int s = wid;

    cpa16(sbase + OG_OFF + tid * 16, og + (size_t)b * H_DIM + tid * 4);
    const float* erow = enh + ((size_t)s * B_DIM + b) * H_DIM;
    #pragma unroll
    for (int j = 0; j < 16; j++) {
        const int slot = lid + j * 32;
        cpa16(sbase + SE_OFF + (s * (H_DIM / 4) + slot) * 16, erow + slot * 4);
    }
    CP_COMMIT();
    CP_WAIT0();
    __syncthreads();

    float dot = 0.f, e2 = 0.f, o2 = 0.f;
    #pragma unroll
    for (int j = 0; j < 16; j++) {
        const int slot = lid + j * 32;
        float4 ov = ogs[slot];
        float4 v  = se[s * (H_DIM / 4) + slot];
        dot += dot4(v, ov);
        e2  += dot4(v, v);
        o2  += dot4(ov, ov);
    }
    #pragma unroll
    for (int o = 16; o; o >>= 1) {
        dot += __shfl_xor_sync(0xffffffffu, dot, o);
        e2  += __shfl_xor_sync(0xffffffffu, e2, o);
        o2  += __shfl_xor_sync(0xffffffffu, o2, o);
    }
    if (lid == 0) {
        const float denom = fmaxf(sqrtf(e2) * sqrtf(o2), EPS);
        sh_sims[s] = (dot / denom) * (1.0f / S_DIM);
    }
    __syncthreads();

    float w[S_DIM];
    #pragma unroll
    for (int k = 0; k < S_DIM; k++) w[k] = sh_sims[k];

    float4 acc = make_float4(0.f, 0.f, 0.f, 0.f);
    #pragma unroll
    for (int k = 0; k < S_DIM; k++) {
        float4 v = se[k * (H_DIM / 4) + tid];
        acc.x += v.x * w[k]; acc.y += v.y * w[k];
        acc.z += v.z * w[k]; acc.w += v.w * w[k];
    }
    uint32_t h0, l0, h1, l1;
    split2h(acc.x, acc.y, h0, l0);
    split2h(acc.z, acc.w, h1, l1);
    const size_t o = (size_t)b * H_DIM + (size_t)tid * 4;
    *reinterpret_cast<uint2*>(g_Ahi + o) = make_uint2(h0, h1);
    *reinterpret_cast<uint2*>(g_Alo + o) = make_uint2(l0, l1);
}

// ---------------------------------------------------------------------------
// Kernel 2: HMMA GEMM  out = wr @ W^T + b   (R15 version, measured 42.6us)
// 2-product fp16 split, KT=64, 4-stage A cp.async, B fp32 reg-prefetch +
// fp16 cvt double-buffered; 512 threads, ks-split across two warpsets.
// ---------------------------------------------------------------------------
#define MT 128
#define NT 64
#define KT 64
#define NKC (H_DIM / KT)        // 32
#define LDS 144                 // bytes per smem row (72 fp16)
#define OFF_ALO (MT * LDS)                  // 18432
#define ASTAGE  (2 * MT * LDS)              // 36864
#define BBASE   (4 * ASTAGE)                // 147456
#define BSTAGE  (NT * LDS)                  // 9216 (hi only)
#define SM_GEMM (BBASE + 2 * BSTAGE)        // 165888

__global__ void __launch_bounds__(512, 1)
gemm_hmma(const float* __restrict__ Wm, const float* __restrict__ bias,
          float* __restrict__ out) {
    extern __shared__ __align__(16) char sm[];
    const uint32_t sbase = smem_u32(sm);
    const int tid = threadIdx.x;
    const int wid = tid >> 5;           // 0..15
    const int l   = tid & 31;
    const int kset = wid >> 3;          // 0: ks 0-1, 1: ks 2-3
    const int wg   = wid & 7;           // warp within set
    const int bn = blockIdx.x;          // N tile (32)
    const int bm = blockIdx.y;          // M tile (4)

    const __half* gAhi = g_Ahi + (size_t)bm * MT * H_DIM;
    const __half* gAlo = g_Alo + (size_t)bm * MT * H_DIM;

    // A loader: 512 threads; row = tid>>2 (0..127), 2 16B-chunks at (tid&3)*2
    const int arow = tid >> 2;
    const int acb  = (tid & 3) * 2;
    auto load_stageA = [&](int buf, int kb) {
        const uint32_t sb = sbase + buf * ASTAGE + arow * LDS;
        const __half* sh = gAhi + (size_t)arow * H_DIM + kb * KT;
        const __half* sl = gAlo + (size_t)arow * H_DIM + kb * KT;
        #pragma unroll
        for (int f = 0; f < 2; f++) {
            const int c = acb + f;
            cpa16(sb + c * 16, sh + c * 8);
            cpa16(sb + c * 16 + OFF_ALO, sl + c * 8);
        }
    };

    // B loader: 512 threads; row = tid>>3 (0..63), 8-float seg at (tid&7)*8
    const int brow = tid >> 3;
    const int bq   = (tid & 7) * 8;
    const float* wrow = Wm + (size_t)(bn * NT + brow) * H_DIM + bq;

    float4 breg[2];
    auto ldg_B = [&](int kb) {
        const float* p = wrow + kb * KT;
        breg[0] = *reinterpret_cast<const float4*>(p);
        breg[1] = *reinterpret_cast<const float4*>(p + 4);
    };
    auto sts_B = [&](int buf) {
        const uint32_t bb = BBASE + buf * BSTAGE + brow * LDS + bq * 2;
        uint32_t h0 = cvt2h(breg[0].x, breg[0].y);
        uint32_t h1 = cvt2h(breg[0].z, breg[0].w);
        uint32_t h2 = cvt2h(breg[1].x, breg[1].y);
        uint32_t h3 = cvt2h(breg[1].z, breg[1].w);
        *reinterpret_cast<uint4*>(sm + bb) = make_uint4(h0, h1, h2, h3);
    };

    // prologue: A stages 0,1,2 in flight; B(0) in smem, B(1) in regs
    ldg_B(0);
    load_stageA(0, 0); CP_COMMIT();
    load_stageA(1, 1); CP_COMMIT();
    load_stageA(2, 2); CP_COMMIT();
    sts_B(0);
    ldg_B(1);

    const int m0 = (wg & 3) * 32;
    const int n0 = (wg >> 2) * 32;

    const uint32_t aoff = (uint32_t)(((l & 7) + ((l >> 3) & 1) * 8) * LDS
                                     + ((l >> 4) & 1) * 16);
    const uint32_t boff = (uint32_t)(((l & 7) + ((l >> 4) & 1) * 8) * LDS
                                     + ((l >> 3) & 1) * 16);

    float acc[2][4][4];
    #pragma unroll
    for (int mi = 0; mi < 2; mi++)
        #pragma unroll
        for (int nj = 0; nj < 4; nj++)
            #pragma unroll
            for (int q = 0; q < 4; q++) acc[mi][nj][q] = 0.f;

    for (int kc = 0; kc < NKC; kc++) {
        CP_WAIT2();                       // A stage kc resident
        __syncthreads();                  // B buffer (kc&1) published

        const uint32_t sa = sbase + (kc & 3) * ASTAGE;
        const uint32_t sb = sbase + BBASE + (kc & 1) * BSTAGE;
        const uint32_t aHiB = sa + m0 * LDS + aoff;
        const uint32_t aLoB = sa + OFF_ALO + m0 * LDS + aoff;
        const uint32_t bHiB = sb + n0 * LDS + boff;

        if (kc + 1 < NKC) sts_B((kc + 1) & 1);
        if (kc + 3 < NKC) load_stageA((kc + 3) & 3, kc + 3);
        CP_COMMIT();
        if (kc + 2 < NKC) ldg_B(kc + 2);

        // this warpset's half of the chunk: ks in {kset*2, kset*2+1}
        #pragma unroll
        for (int kk = 0; kk < 2; kk++) {
            const int ks = kset * 2 + kk;
            uint32_t ah[2][4], al[2][4], bh[2][4];
            #pragma unroll
            for (int mi = 0; mi < 2; mi++) {
                ldsm4(ah[mi], aHiB + mi * 16 * LDS + ks * 32);
                ldsm4(al[mi], aLoB + mi * 16 * LDS + ks * 32);
            }
            #pragma unroll
            for (int ng = 0; ng < 2; ng++)
                ldsm4(bh[ng], bHiB + ng * 16 * LDS + ks * 32);

            #pragma unroll
            for (int mi = 0; mi < 2; mi++)
                #pragma unroll
                for (int nj = 0; nj < 4; nj++) {
                    const int ng = nj >> 1, sp = (nj & 1) * 2;
                    mma16816(acc[mi][nj], ah[mi], bh[ng][sp], bh[ng][sp + 1]);
                }
            #pragma unroll
            for (int mi = 0; mi < 2; mi++)
                #pragma unroll
                for (int nj = 0; nj < 4; nj++) {
                    const int ng = nj >> 1, sp = (nj & 1) * 2;
                    mma16816(acc[mi][nj], al[mi], bh[ng][sp], bh[ng][sp + 1]);
                }
        }
    }

    // merge the two half-K accumulators (reuse stage smem), then epilogue
    __syncthreads();
    float* red = reinterpret_cast<float*>(sm);
    const int t = tid & 255;             // matching (wg, l) across sets
    if (kset == 1) {
        int i = 0;
        #pragma unroll
        for (int mi = 0; mi < 2; mi++)
            #pragma unroll
            for (int nj = 0; nj < 4; nj++)
                #pragma unroll
                for (int q = 0; q < 4; q++) red[t * 32 + (i++)] = acc[mi][nj][q];
    }
    __syncthreads();
    if (kset == 0) {
        int i = 0;
        #pragma unroll
        for (int mi = 0; mi < 2; mi++)
            #pragma unroll
            for (int nj = 0; nj < 4; nj++)
                #pragma unroll
                for (int q = 0; q < 4; q++) acc[mi][nj][q] += red[t * 32 + (i++)];

        #pragma unroll
        for (int mi = 0; mi < 2; mi++) {
            const int row = bm * MT + m0 + mi * 16 + (l >> 2);
            #pragma unroll
            for (int nj = 0; nj < 4; nj++) {
                const int gcol = bn * NT + n0 + nj * 8 + (l & 3) * 2;
                const float b0 = bias[gcol], b1 = bias[gcol + 1];
                float2 v0 = make_float2(acc[mi][nj][0] + b0, acc[mi][nj][1] + b1);
                float2 v1 = make_float2(acc[mi][nj][2] + b0, acc[mi][nj][3] + b1);
                *reinterpret_cast<float2*>(out + (size_t)row * H_DIM + gcol) = v0;
                *reinterpret_cast<float2*>(out + (size_t)(row + 8) * H_DIM + gcol) = v1;
            }
        }
    }
}

// ---------------------------------------------------------------------------
extern "C" void kernel_launch(void* const* d_in, const int* in_sizes, int n_in,
                              void* d_out, int out_size) {
    const float* og   = (const float*)d_in[0];   // (B, H)
    const float* enh  = (const float*)d_in[1];   // (S, B, H)
    const float* Wm   = (const float*)d_in[2];   // (H, H)
    const float* bias = (const float*)d_in[3];   // (H,)
    float* out = (float*)d_out;                  // (B, H)

    cudaFuncSetAttribute(gemm_hmma, cudaFuncAttributeMaxDynamicSharedMemorySize,
                         SM_GEMM);
    cudaFuncSetAttribute(fused_prep, cudaFuncAttributeMaxDynamicSharedMemorySize,
                         FUSED_SMEM);

    fused_prep<<<B_DIM, 512, FUSED_SMEM>>>(og, enh);
    gemm_hmma<<<dim3(H_DIM / NT, B_DIM / MT), 512, SM_GEMM>>>(Wm, bias, out);
}

// round 17
// speedup vs baseline: 1.1307x; 1.1307x over previous
#include <cuda_runtime.h>
#include <cuda_fp16.h>
#include <math.h>
#include <stdint.h>

#define S_DIM 16
#define B_DIM 512
#define H_DIM 2048
#define EPS 1e-8f

// ---------------------------------------------------------------------------
// Device scratch (fp16 hi/lo of weightedRep)
// ---------------------------------------------------------------------------
__device__ __align__(16) __half g_Ahi[B_DIM * H_DIM];
__device__ __align__(16) __half g_Alo[B_DIM * H_DIM];

// ---------------------------------------------------------------------------
// PTX helpers (sm_80/90 baseline only — harness PTX target is sm_103, no 'a')
// ---------------------------------------------------------------------------
__device__ __forceinline__ uint32_t smem_u32(const void* p) {
    uint32_t r;
    asm("{ .reg .u64 t; cvta.to.shared.u64 t, %1; cvt.u32.u64 %0, t; }"
        : "=r"(r) : "l"(p));
    return r;
}
__device__ __forceinline__ void cpa16(uint32_t dst, const void* src) {
    asm volatile("cp.async.cg.shared.global [%0], [%1], 16;" :: "r"(dst), "l"(src));
}
#define CP_COMMIT() asm volatile("cp.async.commit_group;" ::: "memory")
#define CP_WAIT2()  asm volatile("cp.async.wait_group 2;" ::: "memory")

__device__ __forceinline__ void ldsm4(uint32_t* r, uint32_t addr) {
    asm volatile("ldmatrix.sync.aligned.m8n8.x4.shared.b16 {%0,%1,%2,%3}, [%4];"
                 : "=r"(r[0]), "=r"(r[1]), "=r"(r[2]), "=r"(r[3]) : "r"(addr));
}
// fp16 MMA, fp32 accum
__device__ __forceinline__ void mma16816(float* d, const uint32_t* a,
                                         uint32_t b0, uint32_t b1) {
    asm volatile(
        "mma.sync.aligned.m16n8k16.row.col.f32.f16.f16.f32 "
        "{%0,%1,%2,%3}, {%4,%5,%6,%7}, {%8,%9}, {%0,%1,%2,%3};"
        : "+f"(d[0]), "+f"(d[1]), "+f"(d[2]), "+f"(d[3])
        : "r"(a[0]), "r"(a[1]), "r"(a[2]), "r"(a[3]), "r"(b0), "r"(b1));
}
__device__ __forceinline__ float dot4(float4 a, float4 b) {
    return a.x * b.x + a.y * b.y + a.z * b.z + a.w * b.w;
}
// fp32 pair -> fp16 hi pair + fp16 lo pair (packed u32); hi+lo ~= exact
__device__ __forceinline__ void split2h(float x, float y, uint32_t& h, uint32_t& l) {
    __half2 hh = __floats2half2_rn(x, y);
    float hx = __half2float(__low2half(hh));
    float hy = __half2float(__high2half(hh));
    __half2 ll = __floats2half2_rn(x - hx, y - hy);
    h = *reinterpret_cast<uint32_t*>(&hh);
    l = *reinterpret_cast<uint32_t*>(&ll);
}
__device__ __forceinline__ uint32_t cvt2h(float x, float y) {
    __half2 hh = __floats2half2_rn(x, y);
    return *reinterpret_cast<uint32_t*>(&hh);
}

// ---------------------------------------------------------------------------
// Kernel 1 (fused): norms + sims + weightedRep -> fp16 hi/lo
// One CTA per b, 512 threads, warp w owns sample s = w.
// enhanced staged in smem as FP16 (64KB -> 2 CTAs/SM); sims computed in
// full fp32 from the register stream. Only the weighted sum uses fp16 e.
// ---------------------------------------------------------------------------
#define FUSED_SMEM (S_DIM * H_DIM * 2)               // 65536

__global__ void __launch_bounds__(512, 2)
fused_prep(const float* __restrict__ og, const float* __restrict__ enh) {
    extern __shared__ __align__(16) __half2 seh[];   // [S_DIM][H_DIM/2]
    __shared__ float sh_sims[S_DIM];

    const int b = blockIdx.x;
    const int tid = threadIdx.x;
    const int wid = tid >> 5, lid = tid & 31;
    const int s = wid;

    const float4* og4 = reinterpret_cast<const float4*>(og) + (size_t)b * (H_DIM / 4);
    const float4* e4  = reinterpret_cast<const float4*>(enh)
                        + ((size_t)s * B_DIM + b) * (H_DIM / 4);

    float dot = 0.f, e2 = 0.f, o2 = 0.f;
    #pragma unroll
    for (int batch = 0; batch < 4; batch++) {
        float4 v[4], ov[4];
        #pragma unroll
        for (int j = 0; j < 4; j++) {
            const int slot = lid + (batch * 4 + j) * 32;
            v[j]  = e4[slot];
            ov[j] = og4[slot];
        }
        #pragma unroll
        for (int j = 0; j < 4; j++) {
            const int slot = lid + (batch * 4 + j) * 32;
            dot += dot4(v[j], ov[j]);
            e2  += dot4(v[j], v[j]);
            o2  += dot4(ov[j], ov[j]);
            seh[s * (H_DIM / 2) + slot * 2]     = __floats2half2_rn(v[j].x, v[j].y);
            seh[s * (H_DIM / 2) + slot * 2 + 1] = __floats2half2_rn(v[j].z, v[j].w);
        }
    }
    #pragma unroll
    for (int o = 16; o; o >>= 1) {
        dot += __shfl_xor_sync(0xffffffffu, dot, o);
        e2  += __shfl_xor_sync(0xffffffffu, e2, o);
        o2  += __shfl_xor_sync(0xffffffffu, o2, o);
    }
    if (lid == 0) {
        const float denom = fmaxf(sqrtf(e2) * sqrtf(o2), EPS);
        sh_sims[s] = (dot / denom) * (1.0f / S_DIM);
    }
    __syncthreads();

    float w[S_DIM];
    #pragma unroll
    for (int k = 0; k < S_DIM; k++) w[k] = sh_sims[k];

    float4 acc = make_float4(0.f, 0.f, 0.f, 0.f);
    #pragma unroll
    for (int k = 0; k < S_DIM; k++) {
        const __half2 p0 = seh[k * (H_DIM / 2) + tid * 2];
        const __half2 p1 = seh[k * (H_DIM / 2) + tid * 2 + 1];
        const float2 f0 = __half22float2(p0);
        const float2 f1 = __half22float2(p1);
        acc.x += f0.x * w[k]; acc.y += f0.y * w[k];
        acc.z += f1.x * w[k]; acc.w += f1.y * w[k];
    }
    uint32_t h0, l0, h1, l1;
    split2h(acc.x, acc.y, h0, l0);
    split2h(acc.z, acc.w, h1, l1);
    const size_t o = (size_t)b * H_DIM + (size_t)tid * 4;
    *reinterpret_cast<uint2*>(g_Ahi + o) = make_uint2(h0, h1);
    *reinterpret_cast<uint2*>(g_Alo + o) = make_uint2(l0, l1);
}

// ---------------------------------------------------------------------------
// Kernel 2: HMMA GEMM  out = wr @ W^T + b   (R12 version — best in-run)
// 2-product fp16 split: D = ah*bh + al*bh. KT=64, 4-stage A cp.async,
// B fp32 reg-prefetch + fp16 cvt double-buffered, 256 threads,
// fragment double-buffering over ks.
// ---------------------------------------------------------------------------
#define MT 128
#define NT 64
#define KT 64
#define NKC (H_DIM / KT)        // 32
#define LDS 144                 // bytes per smem row (72 fp16)
#define OFF_ALO (MT * LDS)                  // 18432
#define ASTAGE  (2 * MT * LDS)              // 36864
#define BBASE   (4 * ASTAGE)                // 147456
#define BSTAGE  (NT * LDS)                  // 9216 (hi only)
#define SM_GEMM (BBASE + 2 * BSTAGE)        // 165888

__global__ void __launch_bounds__(256, 1)
gemm_hmma(const float* __restrict__ Wm, const float* __restrict__ bias,
          float* __restrict__ out) {
    extern __shared__ __align__(16) char sm[];
    const uint32_t sbase = smem_u32(sm);
    const int tid = threadIdx.x;
    const int wid = tid >> 5;
    const int l   = tid & 31;
    const int bn = blockIdx.x;          // N tile (32)
    const int bm = blockIdx.y;          // M tile (4)

    const __half* gAhi = g_Ahi + (size_t)bm * MT * H_DIM;
    const __half* gAlo = g_Alo + (size_t)bm * MT * H_DIM;

    const int lrow = tid >> 3;          // 0..31
    const int lchk = tid & 7;           // 0..7

    auto load_stageA = [&](int buf, int kb) {
        const uint32_t sb = sbase + buf * ASTAGE;
        const int koff = kb * KT + lchk * 8;
        #pragma unroll
        for (int rr = 0; rr < 4; rr++) {
            const int row = rr * 32 + lrow;
            const uint32_t d = sb + row * LDS + lchk * 16;
            cpa16(d, gAhi + (size_t)row * H_DIM + koff);
            cpa16(d + OFF_ALO, gAlo + (size_t)row * H_DIM + koff);
        }
    };

    const int brow = tid >> 2;          // 0..63
    const int bq   = (tid & 3) * 16;    // col base
    const float* wrow = Wm + (size_t)(bn * NT + brow) * H_DIM + bq;

    float4 breg[4];
    auto ldg_B = [&](int kb) {
        const float* p = wrow + kb * KT;
        #pragma unroll
        for (int f = 0; f < 4; f++)
            breg[f] = *reinterpret_cast<const float4*>(p + f * 4);
    };
    auto sts_B = [&](int buf) {
        const uint32_t bb = BBASE + buf * BSTAGE + brow * LDS + bq * 2;
        #pragma unroll
        for (int f = 0; f < 2; f++) {
            uint32_t h0 = cvt2h(breg[f * 2].x, breg[f * 2].y);
            uint32_t h1 = cvt2h(breg[f * 2].z, breg[f * 2].w);
            uint32_t h2 = cvt2h(breg[f * 2 + 1].x, breg[f * 2 + 1].y);
            uint32_t h3 = cvt2h(breg[f * 2 + 1].z, breg[f * 2 + 1].w);
            *reinterpret_cast<uint4*>(sm + bb + f * 16) = make_uint4(h0, h1, h2, h3);
        }
    };

    // prologue: A stages 0,1,2 in flight; B(0) in smem, B(1) in regs
    ldg_B(0);
    load_stageA(0, 0); CP_COMMIT();
    load_stageA(1, 1); CP_COMMIT();
    load_stageA(2, 2); CP_COMMIT();
    sts_B(0);
    ldg_B(1);

    const int m0 = (wid & 3) * 32;
    const int n0 = (wid >> 2) * 32;

    const uint32_t aoff = (uint32_t)(((l & 7) + ((l >> 3) & 1) * 8) * LDS
                                     + ((l >> 4) & 1) * 16);
    const uint32_t boff = (uint32_t)(((l & 7) + ((l >> 4) & 1) * 8) * LDS
                                     + ((l >> 3) & 1) * 16);

    float acc[2][4][4];
    #pragma unroll
    for (int mi = 0; mi < 2; mi++)
        #pragma unroll
        for (int nj = 0; nj < 4; nj++)
            #pragma unroll
            for (int q = 0; q < 4; q++) acc[mi][nj][q] = 0.f;

    uint32_t ah[2][2][4], al[2][2][4], bh[2][2][4];

    for (int kc = 0; kc < NKC; kc++) {
        CP_WAIT2();                       // A stage kc resident
        __syncthreads();                  // B buffer (kc&1) published

        const uint32_t sa = sbase + (kc & 3) * ASTAGE;
        const uint32_t sb = sbase + BBASE + (kc & 1) * BSTAGE;
        const uint32_t aHiB = sa + m0 * LDS + aoff;
        const uint32_t aLoB = sa + OFF_ALO + m0 * LDS + aoff;
        const uint32_t bHiB = sb + n0 * LDS + boff;

        #pragma unroll
        for (int mi = 0; mi < 2; mi++) {
            ldsm4(ah[0][mi], aHiB + mi * 16 * LDS);
            ldsm4(al[0][mi], aLoB + mi * 16 * LDS);
        }
        #pragma unroll
        for (int ng = 0; ng < 2; ng++)
            ldsm4(bh[0][ng], bHiB + ng * 16 * LDS);

        if (kc + 1 < NKC) sts_B((kc + 1) & 1);
        if (kc + 3 < NKC) load_stageA((kc + 3) & 3, kc + 3);
        CP_COMMIT();
        if (kc + 2 < NKC) ldg_B(kc + 2);

        #pragma unroll
        for (int ks = 0; ks < 4; ks++) {
            const int cur = ks & 1, nxt = cur ^ 1;
            if (ks < 3) {
                #pragma unroll
                for (int mi = 0; mi < 2; mi++) {
                    ldsm4(ah[nxt][mi], aHiB + mi * 16 * LDS + (ks + 1) * 32);
                    ldsm4(al[nxt][mi], aLoB + mi * 16 * LDS + (ks + 1) * 32);
                }
                #pragma unroll
                for (int ng = 0; ng < 2; ng++)
                    ldsm4(bh[nxt][ng], bHiB + ng * 16 * LDS + (ks + 1) * 32);
            }
            #pragma unroll
            for (int mi = 0; mi < 2; mi++) {
                #pragma unroll
                for (int nj = 0; nj < 4; nj++) {
                    const int ng = nj >> 1, sp = (nj & 1) * 2;
                    mma16816(acc[mi][nj], ah[cur][mi], bh[cur][ng][sp], bh[cur][ng][sp + 1]);
                    mma16816(acc[mi][nj], al[cur][mi], bh[cur][ng][sp], bh[cur][ng][sp + 1]);
                }
            }
        }
    }

    // epilogue
    #pragma unroll
    for (int mi = 0; mi < 2; mi++) {
        const int row = bm * MT + m0 + mi * 16 + (l >> 2);
        #pragma unroll
        for (int nj = 0; nj < 4; nj++) {
            const int gcol = bn * NT + n0 + nj * 8 + (l & 3) * 2;
            const float b0 = bias[gcol], b1 = bias[gcol + 1];
            float2 v0 = make_float2(acc[mi][nj][0] + b0, acc[mi][nj][1] + b1);
            float2 v1 = make_float2(acc[mi][nj][2] + b0, acc[mi][nj][3] + b1);
            *reinterpret_cast<float2*>(out + (size_t)row * H_DIM + gcol) = v0;
            *reinterpret_cast<float2*>(out + (size_t)(row + 8) * H_DIM + gcol) = v1;
        }
    }
}

// ---------------------------------------------------------------------------
extern "C" void kernel_launch(void* const* d_in, const int* in_sizes, int n_in,
                              void* d_out, int out_size) {
    const float* og   = (const float*)d_in[0];   // (B, H)
    const float* enh  = (const float*)d_in[1];   // (S, B, H)
    const float* Wm   = (const float*)d_in[2];   // (H, H)
    const float* bias = (const float*)d_in[3];   // (H,)
    float* out = (float*)d_out;                  // (B, H)

    cudaFuncSetAttribute(gemm_hmma, cudaFuncAttributeMaxDynamicSharedMemorySize,
                         SM_GEMM);
    cudaFuncSetAttribute(fused_prep, cudaFuncAttributeMaxDynamicSharedMemorySize,
                         FUSED_SMEM);

    fused_prep<<<B_DIM, 512, FUSED_SMEM>>>(og, enh);
    gemm_hmma<<<dim3(H_DIM / NT, B_DIM / MT), 256, SM_GEMM>>>(Wm, bias, out);
}